// round 1
// baseline (speedup 1.0000x reference)
#include <cuda_runtime.h>
#include <math.h>

#define Bb 2
#define Ss 2048
#define Ee 2048
#define Hh 16
#define Dh 128

// Scratch (allocation-free rule: __device__ globals)
__device__ float g_q[(size_t)Bb * Hh * Ss * Dh];
__device__ float g_k[(size_t)Bb * Hh * Ss * Dh];
__device__ float g_v[(size_t)Bb * Hh * Ss * Dh];
__device__ float g_ao[(size_t)Bb * Ss * Ee];

// ---------------------------------------------------------------------------
// Tiled fp32 TN GEMM: C[M,N] = A[M,K] * B[N,K]^T  (both K-contiguous)
// MODE 0: plain store to C.  MODE 1: scatter into g_q/g_k/g_v per the
// qkv.reshape(b,s,8,768)->split->reshape(b,s,16,128) mapping, layout [B,H,S,D].
// ---------------------------------------------------------------------------
template <int MODE>
__global__ __launch_bounds__(256) void sgemm_tn(
    const float* __restrict__ A, const float* __restrict__ Bw,
    float* __restrict__ C, int M, int N, int K)
{
    __shared__ __align__(16) float As[16][132];
    __shared__ __align__(16) float Bs[16][132];

    const int tid = threadIdx.x;
    const int tx = tid & 15;       // 0..15 -> output cols
    const int ty = tid >> 4;       // 0..15 -> output rows
    const int brow = blockIdx.y * 128;
    const int bcol = blockIdx.x * 128;

    float c[8][8];
#pragma unroll
    for (int i = 0; i < 8; i++)
#pragma unroll
        for (int j = 0; j < 8; j++) c[i][j] = 0.f;

    const int lrow = tid >> 2;        // 0..63
    const int lk   = (tid & 3) * 4;   // 0,4,8,12
    const float* Ag = A  + (size_t)(brow + lrow) * K + lk;
    const float* Bg = Bw + (size_t)(bcol + lrow) * K + lk;

    for (int k0 = 0; k0 < K; k0 += 16) {
        float4 va0 = *(const float4*)(Ag + k0);
        float4 va1 = *(const float4*)(Ag + (size_t)64 * K + k0);
        float4 vb0 = *(const float4*)(Bg + k0);
        float4 vb1 = *(const float4*)(Bg + (size_t)64 * K + k0);

        As[lk + 0][lrow] = va0.x; As[lk + 1][lrow] = va0.y;
        As[lk + 2][lrow] = va0.z; As[lk + 3][lrow] = va0.w;
        As[lk + 0][lrow + 64] = va1.x; As[lk + 1][lrow + 64] = va1.y;
        As[lk + 2][lrow + 64] = va1.z; As[lk + 3][lrow + 64] = va1.w;

        Bs[lk + 0][lrow] = vb0.x; Bs[lk + 1][lrow] = vb0.y;
        Bs[lk + 2][lrow] = vb0.z; Bs[lk + 3][lrow] = vb0.w;
        Bs[lk + 0][lrow + 64] = vb1.x; Bs[lk + 1][lrow + 64] = vb1.y;
        Bs[lk + 2][lrow + 64] = vb1.z; Bs[lk + 3][lrow + 64] = vb1.w;

        __syncthreads();
#pragma unroll
        for (int kk = 0; kk < 16; kk++) {
            float4 a0 = *(const float4*)&As[kk][ty * 8];
            float4 a1 = *(const float4*)&As[kk][ty * 8 + 4];
            float4 b0 = *(const float4*)&Bs[kk][tx * 8];
            float4 b1 = *(const float4*)&Bs[kk][tx * 8 + 4];
            float av[8] = {a0.x, a0.y, a0.z, a0.w, a1.x, a1.y, a1.z, a1.w};
            float bv[8] = {b0.x, b0.y, b0.z, b0.w, b1.x, b1.y, b1.z, b1.w};
#pragma unroll
            for (int i = 0; i < 8; i++)
#pragma unroll
                for (int j = 0; j < 8; j++) c[i][j] += av[i] * bv[j];
        }
        __syncthreads();
    }

    if constexpr (MODE == 0) {
#pragma unroll
        for (int i = 0; i < 8; i++) {
            int row = brow + ty * 8 + i;
            float4* Cp = (float4*)(C + (size_t)row * N + bcol + tx * 8);
            Cp[0] = make_float4(c[i][0], c[i][1], c[i][2], c[i][3]);
            Cp[1] = make_float4(c[i][4], c[i][5], c[i][6], c[i][7]);
        }
    } else {
#pragma unroll
        for (int i = 0; i < 8; i++) {
            int row = brow + ty * 8 + i;
            int bb = row >> 11;         // / S (2048)
            int ss = row & 2047;
#pragma unroll
            for (int j = 0; j < 8; j++) {
                int f  = bcol + tx * 8 + j;
                int mp = f / 768;
                int r  = f - mp * 768;
                int which = r >> 8;     // 0=q,1=k,2=v
                int cc = r & 255;
                int hh = mp * 2 + (cc >> 7);
                int dd = cc & 127;
                float* dst = (which == 0) ? g_q : ((which == 1) ? g_k : g_v);
                dst[((((size_t)bb * Hh + hh) * Ss + ss) << 7) + dd] = c[i][j];
            }
        }
    }
}

// ---------------------------------------------------------------------------
// RoPE on first 32 dims of q,k.  One thread per (b,h,s,pair).
// out[2i]   = x[2i]*cos(s*w_i) - x[2i+1]*sin(s*w_i)
// out[2i+1] = x[2i+1]*cos(s*w_i) + x[2i]*sin(s*w_i),  w_i = 10000^(-i/16)
// ---------------------------------------------------------------------------
__global__ void rope_kernel()
{
    int idx = blockIdx.x * blockDim.x + threadIdx.x;  // B*Hh*Ss*16 total
    int i  = idx & 15;
    int s  = (idx >> 4) & (Ss - 1);
    int bh = idx >> 15;
    float inv_freq = powf(10000.f, -(float)i / 16.f);
    float ang = (float)s * inv_freq;
    float sn, cs;
    sincosf(ang, &sn, &cs);
    size_t base = (((size_t)bh * Ss + s) << 7) + 2 * i;
    float x0 = g_q[base], x1 = g_q[base + 1];
    g_q[base]     = x0 * cs - x1 * sn;
    g_q[base + 1] = x1 * cs + x0 * sn;
    x0 = g_k[base]; x1 = g_k[base + 1];
    g_k[base]     = x0 * cs - x1 * sn;
    g_k[base + 1] = x1 * cs + x0 * sn;
}

// ---------------------------------------------------------------------------
// Flash attention, fp32, causal.  Block = 64 q rows x 256 threads.
// Thread (row=tid>>2, q4=tid&3) owns dims [q4*32, q4*32+32).
// KV tiles of 32 rows staged in smem (32 KB).  Online softmax.
// Output written directly in [B,S,E] layout for the final GEMM.
// ---------------------------------------------------------------------------
__global__ __launch_bounds__(256) void attn_kernel(
    const float* __restrict__ q, const float* __restrict__ k,
    const float* __restrict__ v, float* __restrict__ o)
{
    __shared__ __align__(16) float Ks[32 * 128];
    __shared__ __align__(16) float Vs[32 * 128];

    const int qt = blockIdx.x, h = blockIdx.y, b = blockIdx.z;
    const int tid = threadIdx.x;
    const int row = tid >> 2, q4 = tid & 3;
    const int qi = qt * 64 + row;
    const size_t hb = ((size_t)(b * Hh + h)) * Ss * Dh;
    const float scale = 0.08838834764831845f;  // 1/sqrt(128)

    float4 qreg[8];
    const float4* qp = (const float4*)(q + hb + ((size_t)qi << 7) + q4 * 32);
#pragma unroll
    for (int t = 0; t < 8; t++) {
        float4 tmp = qp[t];
        tmp.x *= scale; tmp.y *= scale; tmp.z *= scale; tmp.w *= scale;
        qreg[t] = tmp;
    }
    float4 acc[8];
#pragma unroll
    for (int t = 0; t < 8; t++) acc[t] = make_float4(0.f, 0.f, 0.f, 0.f);
    float m = -1e30f, l = 0.f;

    const int jend = qt * 64 + 64;  // causal: only tiles with keys <= last q row
    for (int j0 = 0; j0 < jend; j0 += 32) {
        __syncthreads();
        const float4* kg = (const float4*)(k + hb + ((size_t)j0 << 7));
        const float4* vg = (const float4*)(v + hb + ((size_t)j0 << 7));
        float4* K4 = (float4*)Ks;
        float4* V4 = (float4*)Vs;
#pragma unroll
        for (int i = 0; i < 4; i++) {
            K4[tid + i * 256] = kg[tid + i * 256];
            V4[tid + i * 256] = vg[tid + i * 256];
        }
        __syncthreads();

#pragma unroll 1
        for (int jc = 0; jc < 32; jc += 16) {
            float sc[16];
#pragma unroll
            for (int jj = 0; jj < 16; jj++) {
                const float4* kr = (const float4*)(Ks + (jc + jj) * 128 + q4 * 32);
                float s0 = 0.f, s1 = 0.f, s2 = 0.f, s3 = 0.f;
#pragma unroll
                for (int t = 0; t < 8; t++) {
                    float4 kk4 = kr[t];
                    s0 += qreg[t].x * kk4.x; s1 += qreg[t].y * kk4.y;
                    s2 += qreg[t].z * kk4.z; s3 += qreg[t].w * kk4.w;
                }
                float sum = (s0 + s1) + (s2 + s3);
                sum += __shfl_xor_sync(0xffffffffu, sum, 1);
                sum += __shfl_xor_sync(0xffffffffu, sum, 2);
                sc[jj] = (j0 + jc + jj > qi) ? -1e9f : sum;
            }
            float mc = sc[0];
#pragma unroll
            for (int jj = 1; jj < 16; jj++) mc = fmaxf(mc, sc[jj]);
            float mnew = fmaxf(m, mc);
            float corr = __expf(m - mnew);
            m = mnew;
            l *= corr;
#pragma unroll
            for (int t = 0; t < 8; t++) {
                acc[t].x *= corr; acc[t].y *= corr;
                acc[t].z *= corr; acc[t].w *= corr;
            }
#pragma unroll
            for (int jj = 0; jj < 16; jj++) {
                float p = __expf(sc[jj] - mnew);
                l += p;
                const float4* vr = (const float4*)(Vs + (jc + jj) * 128 + q4 * 32);
#pragma unroll
                for (int t = 0; t < 8; t++) {
                    float4 vv = vr[t];
                    acc[t].x += p * vv.x; acc[t].y += p * vv.y;
                    acc[t].z += p * vv.z; acc[t].w += p * vv.w;
                }
            }
        }
    }

    float inv_l = 1.f / l;
    float4* op = (float4*)(o + (((size_t)(b * Ss + qi)) << 11) + h * 128 + q4 * 32);
#pragma unroll
    for (int t = 0; t < 8; t++) {
        float4 vv = acc[t];
        vv.x *= inv_l; vv.y *= inv_l; vv.z *= inv_l; vv.w *= inv_l;
        op[t] = vv;
    }
}

// ---------------------------------------------------------------------------
extern "C" void kernel_launch(void* const* d_in, const int* in_sizes, int n_in,
                              void* d_out, int out_size)
{
    const float* hidden = (const float*)d_in[0];   // [B,S,E]
    const float* wqkv   = (const float*)d_in[1];   // [3E,E]
    const float* wout   = (const float*)d_in[2];   // [E,E]
    float* out = (float*)d_out;                    // [B,S,E]

    float *pq, *pk, *pv, *pao;
    cudaGetSymbolAddress((void**)&pq,  g_q);
    cudaGetSymbolAddress((void**)&pk,  g_k);
    cudaGetSymbolAddress((void**)&pv,  g_v);
    cudaGetSymbolAddress((void**)&pao, g_ao);

    // 1) QKV projection + scatter into [B,H,S,D] q/k/v
    {
        dim3 grid(3 * Ee / 128, (Bb * Ss) / 128);  // (48, 32)
        sgemm_tn<1><<<grid, 256>>>(hidden, wqkv, nullptr, Bb * Ss, 3 * Ee, Ee);
    }
    // 2) RoPE in place on q,k (first 32 dims per head)
    {
        int total = Bb * Hh * Ss * 16;
        rope_kernel<<<total / 256, 256>>>();
    }
    // 3) Causal flash attention -> g_ao in [B,S,E]
    {
        dim3 grid(Ss / 64, Hh, Bb);  // (32,16,2)
        attn_kernel<<<grid, 256>>>(pq, pk, pv, pao);
    }
    // 4) Output projection -> d_out
    {
        dim3 grid(Ee / 128, (Bb * Ss) / 128);  // (16, 32)
        sgemm_tn<0><<<grid, 256>>>(pao, wout, out, Bb * Ss, Ee, Ee);
    }
}

// round 2
// speedup vs baseline: 2.4533x; 2.4533x over previous
#include <cuda_runtime.h>
#include <math.h>

#define Bb 2
#define Ss 2048
#define Ee 2048
#define Hh 16
#define Dh 128

// Scratch (allocation-free rule: __device__ globals)
__device__ float g_q[(size_t)Bb * Hh * Ss * Dh];
__device__ float g_k[(size_t)Bb * Hh * Ss * Dh];
__device__ float g_v[(size_t)Bb * Hh * Ss * Dh];
__device__ float g_ao[(size_t)Bb * Ss * Ee];

// ---------------------------------------------------------------------------
// Tiled fp32 TN GEMM: C[M,N] = A[M,K] * B[N,K]^T  (both K-contiguous)
// MODE 0: plain store to C.  MODE 1: scatter into g_q/g_k/g_v per the
// qkv.reshape(b,s,8,768)->split->reshape(b,s,16,128) mapping, layout [B,H,S,D].
// ---------------------------------------------------------------------------
template <int MODE>
__global__ __launch_bounds__(256) void sgemm_tn(
    const float* __restrict__ A, const float* __restrict__ Bw,
    float* __restrict__ C, int M, int N, int K)
{
    __shared__ __align__(16) float As[16][132];
    __shared__ __align__(16) float Bs[16][132];

    const int tid = threadIdx.x;
    const int tx = tid & 15;       // 0..15 -> output cols
    const int ty = tid >> 4;       // 0..15 -> output rows
    const int brow = blockIdx.y * 128;
    const int bcol = blockIdx.x * 128;

    float c[8][8];
#pragma unroll
    for (int i = 0; i < 8; i++)
#pragma unroll
        for (int j = 0; j < 8; j++) c[i][j] = 0.f;

    const int lrow = tid >> 2;        // 0..63
    const int lk   = (tid & 3) * 4;   // 0,4,8,12
    const float* Ag = A  + (size_t)(brow + lrow) * K + lk;
    const float* Bg = Bw + (size_t)(bcol + lrow) * K + lk;

    for (int k0 = 0; k0 < K; k0 += 16) {
        float4 va0 = *(const float4*)(Ag + k0);
        float4 va1 = *(const float4*)(Ag + (size_t)64 * K + k0);
        float4 vb0 = *(const float4*)(Bg + k0);
        float4 vb1 = *(const float4*)(Bg + (size_t)64 * K + k0);

        As[lk + 0][lrow] = va0.x; As[lk + 1][lrow] = va0.y;
        As[lk + 2][lrow] = va0.z; As[lk + 3][lrow] = va0.w;
        As[lk + 0][lrow + 64] = va1.x; As[lk + 1][lrow + 64] = va1.y;
        As[lk + 2][lrow + 64] = va1.z; As[lk + 3][lrow + 64] = va1.w;

        Bs[lk + 0][lrow] = vb0.x; Bs[lk + 1][lrow] = vb0.y;
        Bs[lk + 2][lrow] = vb0.z; Bs[lk + 3][lrow] = vb0.w;
        Bs[lk + 0][lrow + 64] = vb1.x; Bs[lk + 1][lrow + 64] = vb1.y;
        Bs[lk + 2][lrow + 64] = vb1.z; Bs[lk + 3][lrow + 64] = vb1.w;

        __syncthreads();
#pragma unroll
        for (int kk = 0; kk < 16; kk++) {
            float4 a0 = *(const float4*)&As[kk][ty * 8];
            float4 a1 = *(const float4*)&As[kk][ty * 8 + 4];
            float4 b0 = *(const float4*)&Bs[kk][tx * 8];
            float4 b1 = *(const float4*)&Bs[kk][tx * 8 + 4];
            float av[8] = {a0.x, a0.y, a0.z, a0.w, a1.x, a1.y, a1.z, a1.w};
            float bv[8] = {b0.x, b0.y, b0.z, b0.w, b1.x, b1.y, b1.z, b1.w};
#pragma unroll
            for (int i = 0; i < 8; i++)
#pragma unroll
                for (int j = 0; j < 8; j++) c[i][j] += av[i] * bv[j];
        }
        __syncthreads();
    }

    if constexpr (MODE == 0) {
#pragma unroll
        for (int i = 0; i < 8; i++) {
            int row = brow + ty * 8 + i;
            float4* Cp = (float4*)(C + (size_t)row * N + bcol + tx * 8);
            Cp[0] = make_float4(c[i][0], c[i][1], c[i][2], c[i][3]);
            Cp[1] = make_float4(c[i][4], c[i][5], c[i][6], c[i][7]);
        }
    } else {
#pragma unroll
        for (int i = 0; i < 8; i++) {
            int row = brow + ty * 8 + i;
            int bb = row >> 11;         // / S (2048)
            int ss = row & 2047;
#pragma unroll
            for (int j = 0; j < 8; j++) {
                int f  = bcol + tx * 8 + j;
                int mp = f / 768;
                int r  = f - mp * 768;
                int which = r >> 8;     // 0=q,1=k,2=v
                int cc = r & 255;
                int hh = mp * 2 + (cc >> 7);
                int dd = cc & 127;
                float* dst = (which == 0) ? g_q : ((which == 1) ? g_k : g_v);
                dst[((((size_t)bb * Hh + hh) * Ss + ss) << 7) + dd] = c[i][j];
            }
        }
    }
}

// ---------------------------------------------------------------------------
// RoPE on first 32 dims of q,k.
// ---------------------------------------------------------------------------
__global__ void rope_kernel()
{
    int idx = blockIdx.x * blockDim.x + threadIdx.x;  // B*Hh*Ss*16 total
    int i  = idx & 15;
    int s  = (idx >> 4) & (Ss - 1);
    int bh = idx >> 15;
    float inv_freq = powf(10000.f, -(float)i / 16.f);
    float ang = (float)s * inv_freq;
    float sn, cs;
    sincosf(ang, &sn, &cs);
    size_t base = (((size_t)bh * Ss + s) << 7) + 2 * i;
    float x0 = g_q[base], x1 = g_q[base + 1];
    g_q[base]     = x0 * cs - x1 * sn;
    g_q[base + 1] = x1 * cs + x0 * sn;
    x0 = g_k[base]; x1 = g_k[base + 1];
    g_k[base]     = x0 * cs - x1 * sn;
    g_k[base + 1] = x1 * cs + x0 * sn;
}

// ---------------------------------------------------------------------------
// Flash attention v2, GEMM-structured, fp32, causal.
// Block = 256 threads (16x16 thread grid), Q tile = 128 rows, KV tile = 32.
// Q kept transposed+scaled in smem for the whole block. QK and PV are
// outer-product register GEMMs (8x2 scores, 8x8 output micro-tile) so all
// smem reads are either lane-contiguous or 16-way broadcast.
// Dynamic smem: Qs_t[128][132] + Ks_t[128][36] + Vs[32][132] + Ps_t[32][132]
//             = 119808 bytes -> 1 block/SM.
// ---------------------------------------------------------------------------
#define ATTN_SMEM_BYTES 119808

__global__ __launch_bounds__(256) void attn2(
    const float* __restrict__ q, const float* __restrict__ k,
    const float* __restrict__ v, float* __restrict__ o)
{
    extern __shared__ float sm[];
    float* Qs = sm;               // [d 128][r 128] pitch 132 (transposed, scaled)
    float* Ks = sm + 16896;       // [d 128][kv 32] pitch 36 (transposed)
    float* Vs = Ks + 4608;        // [kv 32][d 128] pitch 132
    float* Ps = Vs + 4224;        // [kv 32][r 128] pitch 132 (transposed)

    const int qt = (int)gridDim.x - 1 - (int)blockIdx.x;  // long blocks first
    const int h = blockIdx.y, b = blockIdx.z;
    const int tid = threadIdx.x;
    const int ty = tid >> 4, tx = tid & 15;
    const int qbase = qt * 128;
    const size_t hb = ((size_t)(b * Hh + h)) * Ss * Dh;
    const float scale = 0.08838834764831845f;  // 1/sqrt(128)

    // Load Q tile transposed + scaled (amortized over all kv tiles)
    {
        int r = tid >> 1;
        int d0 = (tid & 1) * 64;
        const float4* qg = (const float4*)(q + hb + ((size_t)(qbase + r) << 7) + d0);
#pragma unroll
        for (int t = 0; t < 16; t++) {
            float4 vv = qg[t];
            int d = d0 + t * 4;
            Qs[(d + 0) * 132 + r] = vv.x * scale;
            Qs[(d + 1) * 132 + r] = vv.y * scale;
            Qs[(d + 2) * 132 + r] = vv.z * scale;
            Qs[(d + 3) * 132 + r] = vv.w * scale;
        }
    }

    float acc[8][8];
#pragma unroll
    for (int i = 0; i < 8; i++)
#pragma unroll
        for (int j = 0; j < 8; j++) acc[i][j] = 0.f;
    float m[8], l[8];
#pragma unroll
    for (int i = 0; i < 8; i++) { m[i] = -1e30f; l[i] = 0.f; }

    const int ntiles = qt * 4 + 4;
    for (int t0 = 0; t0 < ntiles; t0++) {
        const int j0 = t0 * 32;
        __syncthreads();  // Q ready (1st iter) / prev PV + Ps consumers done

        // K tile transposed: lanes span kv -> conflict-free STS
        {
            int kv = tid & 31, c = tid >> 5;  // 8 chunks of 16 dims
            const float4* kg = (const float4*)(k + hb + ((size_t)(j0 + kv) << 7) + c * 16);
#pragma unroll
            for (int t = 0; t < 4; t++) {
                float4 vv = kg[t];
                int d = c * 16 + t * 4;
                Ks[(d + 0) * 36 + kv] = vv.x;
                Ks[(d + 1) * 36 + kv] = vv.y;
                Ks[(d + 2) * 36 + kv] = vv.z;
                Ks[(d + 3) * 36 + kv] = vv.w;
            }
        }
        // V tile direct copy
        {
            int kv = tid >> 3, d0 = (tid & 7) * 16;
            const float4* vg = (const float4*)(v + hb + ((size_t)(j0 + kv) << 7) + d0);
            float4* vs = (float4*)(Vs + kv * 132 + d0);
#pragma unroll
            for (int t = 0; t < 4; t++) vs[t] = vg[t];
        }
        __syncthreads();

        // QK outer-product GEMM: s[8 rows][2 kv cols]
        float s[8][2];
#pragma unroll
        for (int i = 0; i < 8; i++) { s[i][0] = 0.f; s[i][1] = 0.f; }
#pragma unroll 8
        for (int kk = 0; kk < 128; kk++) {
            float4 a0 = *(const float4*)&Qs[kk * 132 + ty * 8];
            float4 a1 = *(const float4*)&Qs[kk * 132 + ty * 8 + 4];
            float2 bb = *(const float2*)&Ks[kk * 36 + tx * 2];
            float av[8] = {a0.x, a0.y, a0.z, a0.w, a1.x, a1.y, a1.z, a1.w};
#pragma unroll
            for (int i = 0; i < 8; i++) {
                s[i][0] += av[i] * bb.x;
                s[i][1] += av[i] * bb.y;
            }
        }

        // Causal mask (only the 4 diagonal tiles of this q block)
        if (j0 + 31 > qbase) {
#pragma unroll
            for (int i = 0; i < 8; i++) {
                int row = qbase + ty * 8 + i;
                if (j0 + tx * 2 + 0 > row) s[i][0] = -1e9f;
                if (j0 + tx * 2 + 1 > row) s[i][1] = -1e9f;
            }
        }

        // Online softmax (row reductions across the 16 tx lanes)
#pragma unroll
        for (int i = 0; i < 8; i++) {
            float cm = fmaxf(s[i][0], s[i][1]);
            cm = fmaxf(cm, __shfl_xor_sync(0xffffffffu, cm, 1));
            cm = fmaxf(cm, __shfl_xor_sync(0xffffffffu, cm, 2));
            cm = fmaxf(cm, __shfl_xor_sync(0xffffffffu, cm, 4));
            cm = fmaxf(cm, __shfl_xor_sync(0xffffffffu, cm, 8));
            float mn = fmaxf(m[i], cm);
            float corr = __expf(m[i] - mn);
            m[i] = mn;
            float p0 = __expf(s[i][0] - mn);
            float p1 = __expf(s[i][1] - mn);
            float ps = p0 + p1;
            ps += __shfl_xor_sync(0xffffffffu, ps, 1);
            ps += __shfl_xor_sync(0xffffffffu, ps, 2);
            ps += __shfl_xor_sync(0xffffffffu, ps, 4);
            ps += __shfl_xor_sync(0xffffffffu, ps, 8);
            l[i] = l[i] * corr + ps;
            Ps[(tx * 2 + 0) * 132 + ty * 8 + i] = p0;
            Ps[(tx * 2 + 1) * 132 + ty * 8 + i] = p1;
#pragma unroll
            for (int j = 0; j < 8; j++) acc[i][j] *= corr;
        }
        __syncthreads();  // Ps visible to all warps

        // PV outer-product GEMM: acc[8][8] += P[128x32] * V[32x128]
#pragma unroll 4
        for (int p = 0; p < 32; p++) {
            float4 pa0 = *(const float4*)&Ps[p * 132 + ty * 8];
            float4 pa1 = *(const float4*)&Ps[p * 132 + ty * 8 + 4];
            float4 vb0 = *(const float4*)&Vs[p * 132 + tx * 8];
            float4 vb1 = *(const float4*)&Vs[p * 132 + tx * 8 + 4];
            float pa[8] = {pa0.x, pa0.y, pa0.z, pa0.w, pa1.x, pa1.y, pa1.z, pa1.w};
            float vb[8] = {vb0.x, vb0.y, vb0.z, vb0.w, vb1.x, vb1.y, vb1.z, vb1.w};
#pragma unroll
            for (int i = 0; i < 8; i++)
#pragma unroll
                for (int j = 0; j < 8; j++) acc[i][j] += pa[i] * vb[j];
        }
    }

    // Epilogue: normalize and write in [B,S,E] layout
#pragma unroll
    for (int i = 0; i < 8; i++) {
        float inv = 1.f / l[i];
        int r = qbase + ty * 8 + i;
        float4* op = (float4*)(o + (((size_t)(b * Ss + r)) << 11) + h * 128 + tx * 8);
        op[0] = make_float4(acc[i][0] * inv, acc[i][1] * inv, acc[i][2] * inv, acc[i][3] * inv);
        op[1] = make_float4(acc[i][4] * inv, acc[i][5] * inv, acc[i][6] * inv, acc[i][7] * inv);
    }
}

// ---------------------------------------------------------------------------
extern "C" void kernel_launch(void* const* d_in, const int* in_sizes, int n_in,
                              void* d_out, int out_size)
{
    const float* hidden = (const float*)d_in[0];   // [B,S,E]
    const float* wqkv   = (const float*)d_in[1];   // [3E,E]
    const float* wout   = (const float*)d_in[2];   // [E,E]
    float* out = (float*)d_out;                    // [B,S,E]

    float *pq, *pk, *pv, *pao;
    cudaGetSymbolAddress((void**)&pq,  g_q);
    cudaGetSymbolAddress((void**)&pk,  g_k);
    cudaGetSymbolAddress((void**)&pv,  g_v);
    cudaGetSymbolAddress((void**)&pao, g_ao);

    // 1) QKV projection + scatter into [B,H,S,D] q/k/v
    {
        dim3 grid(3 * Ee / 128, (Bb * Ss) / 128);  // (48, 32)
        sgemm_tn<1><<<grid, 256>>>(hidden, wqkv, nullptr, Bb * Ss, 3 * Ee, Ee);
    }
    // 2) RoPE in place on q,k (first 32 dims per head)
    {
        int total = Bb * Hh * Ss * 16;
        rope_kernel<<<total / 256, 256>>>();
    }
    // 3) Causal flash attention -> g_ao in [B,S,E]
    {
        cudaFuncSetAttribute(attn2, cudaFuncAttributeMaxDynamicSharedMemorySize,
                             ATTN_SMEM_BYTES);
        dim3 grid(Ss / 128, Hh, Bb);  // (16,16,2)
        attn2<<<grid, 256, ATTN_SMEM_BYTES>>>(pq, pk, pv, pao);
    }
    // 4) Output projection -> d_out
    {
        dim3 grid(Ee / 128, (Bb * Ss) / 128);  // (16, 32)
        sgemm_tn<0><<<grid, 256>>>(pao, wout, out, Bb * Ss, Ee, Ee);
    }
}

// round 4
// speedup vs baseline: 3.7420x; 1.5253x over previous
#include <cuda_runtime.h>
#include <cuda_bf16.h>
#include <math.h>
#include <cstdint>

#define Bb 2
#define Ss 2048
#define Ee 2048
#define Hh 16
#define Dh 128
#define GK 6144          // packed K = 3 * 2048
#define GKC 192          // GK / 32 chunks

// ---------------- scratch (__device__ globals; no allocation allowed) -------
__device__ float g_q[(size_t)Bb * Hh * Ss * Dh];
__device__ float g_k[(size_t)Bb * Hh * Ss * Dh];
__device__ float g_v[(size_t)Bb * Hh * Ss * Dh];
__device__ float g_ao[(size_t)Bb * Ss * Ee];
__device__ __nv_bfloat16 g_a_p[(size_t)Bb * Ss * GK];       // packed activations
__device__ __nv_bfloat16 g_wqkv_p[(size_t)3 * Ee * GK];     // packed Wqkv
__device__ __nv_bfloat16 g_wout_p[(size_t)Ee * GK];         // packed Wout

// ---------------------------------------------------------------------------
// Packing kernels: fp32 -> 3-term bf16 split along K.
// A-pack: [Ah | Ah | Al]   B-pack: [Bh | Bl | Bh]
// A*B ~= Ah*Bh + Ah*Bl + Al*Bh  (drop Al*Bl ~ 2^-18)
// ---------------------------------------------------------------------------
__device__ __forceinline__ void split_bf16(float x, __nv_bfloat16& h, __nv_bfloat16& l) {
    h = __float2bfloat16(x);
    l = __float2bfloat16(x - __bfloat162float(h));
}

template <int ISA>
__global__ __launch_bounds__(256) void pack_kernel(
    const float* __restrict__ src, __nv_bfloat16* __restrict__ dst, int total4)
{
    int i = blockIdx.x * blockDim.x + threadIdx.x;
    if (i >= total4) return;
    int r = i >> 9;            // / (2048/4)
    int k4 = (i & 511) * 4;
    float4 x = *(const float4*)(src + ((size_t)r << 11) + k4);
    __nv_bfloat16 h[4], l[4];
    split_bf16(x.x, h[0], l[0]); split_bf16(x.y, h[1], l[1]);
    split_bf16(x.z, h[2], l[2]); split_bf16(x.w, h[3], l[3]);
    size_t rb = (size_t)r * GK + k4;
    __nv_bfloat162 hp0 = {h[0], h[1]}, hp1 = {h[2], h[3]};
    __nv_bfloat162 lp0 = {l[0], l[1]}, lp1 = {l[2], l[3]};
    *(__nv_bfloat162*)(dst + rb + 0) = hp0; *(__nv_bfloat162*)(dst + rb + 2) = hp1;
    if (ISA) {  // A: [h|h|l]
        *(__nv_bfloat162*)(dst + rb + 2048) = hp0; *(__nv_bfloat162*)(dst + rb + 2050) = hp1;
        *(__nv_bfloat162*)(dst + rb + 4096) = lp0; *(__nv_bfloat162*)(dst + rb + 4098) = lp1;
    } else {    // B: [h|l|h]
        *(__nv_bfloat162*)(dst + rb + 2048) = lp0; *(__nv_bfloat162*)(dst + rb + 2050) = lp1;
        *(__nv_bfloat162*)(dst + rb + 4096) = hp0; *(__nv_bfloat162*)(dst + rb + 4098) = hp1;
    }
}

// ---------------------------------------------------------------------------
// mma.sync bf16 GEMM: C[M,N] = A[M,GK] * B[N,GK]^T (TN, both K-major).
// CTA tile 128x128, 8 warps (2 along M x 4 along N), warp tile 64x32.
// K-chunk 32, double-buffered smem, 80-byte row pitch (20 words) =>
// fragment LDS pattern row*20+kpair is bank-conflict-free.
// ---------------------------------------------------------------------------
__device__ __forceinline__ void mma_bf16(float* c, const uint32_t* a, const uint32_t* b) {
    asm volatile(
        "mma.sync.aligned.m16n8k16.row.col.f32.bf16.bf16.f32 "
        "{%0,%1,%2,%3}, {%4,%5,%6,%7}, {%8,%9}, {%0,%1,%2,%3};"
        : "+f"(c[0]), "+f"(c[1]), "+f"(c[2]), "+f"(c[3])
        : "r"(a[0]), "r"(a[1]), "r"(a[2]), "r"(a[3]), "r"(b[0]), "r"(b[1]));
}

template <int MODE>
__global__ __launch_bounds__(256, 2) void gemm_mma(
    const __nv_bfloat16* __restrict__ A, const __nv_bfloat16* __restrict__ Bw,
    float* __restrict__ C, int Ncols)
{
    // stage s: A words [s*5120, +2560), B words [s*5120+2560, +2560)
    __shared__ __align__(16) uint32_t sm[2 * 5120];

    const int tid = threadIdx.x;
    const int lane = tid & 31, w = tid >> 5;
    const int wm = w & 1, wn = w >> 1;
    const int mbase = blockIdx.y * 128, nbase = blockIdx.x * 128;

    float acc[4][4][4];
#pragma unroll
    for (int i = 0; i < 4; i++)
#pragma unroll
        for (int j = 0; j < 4; j++)
#pragma unroll
            for (int r = 0; r < 4; r++) acc[i][j][r] = 0.f;

    // global load: unit u in [0,512): row=u>>2, seg=u&3 (8 bf16).  u=tid, tid+256.
    const int grow = tid >> 2, gseg = tid & 3;
    const __nv_bfloat16* Ag = A + (size_t)(mbase + grow) * GK + gseg * 8;
    const __nv_bfloat16* Bg = Bw + (size_t)(nbase + grow) * GK + gseg * 8;
    const size_t rstep = (size_t)64 * GK;

    float4 la0, la1, lb0, lb1;
    const int sts_off = grow * 20 + gseg * 4;   // word offset in a stage

#define G_LDG(c) do {                                                          \
    int k0 = (c) * 32;                                                         \
    la0 = *(const float4*)(Ag + k0);                                           \
    la1 = *(const float4*)(Ag + rstep + k0);                                   \
    lb0 = *(const float4*)(Bg + k0);                                           \
    lb1 = *(const float4*)(Bg + rstep + k0);                                   \
} while (0)

#define G_STS(buf) do {                                                        \
    uint32_t* As_ = sm + (buf) * 5120;                                         \
    uint32_t* Bs_ = As_ + 2560;                                                \
    *(float4*)(As_ + sts_off) = la0;                                           \
    *(float4*)(As_ + sts_off + 64 * 20) = la1;                                 \
    *(float4*)(Bs_ + sts_off) = lb0;                                           \
    *(float4*)(Bs_ + sts_off + 64 * 20) = lb1;                                 \
} while (0)

    G_LDG(0);
    G_STS(0);
    __syncthreads();

    const int awbase = wm * 64 + (lane >> 2);
    const int bwbase = wn * 32 + (lane >> 2);
    const int kp = lane & 3;

    for (int c = 0; c < GKC; c++) {
        const int buf = c & 1;
        if (c + 1 < GKC) G_LDG(c + 1);

        const uint32_t* As_ = sm + buf * 5120;
        const uint32_t* Bs_ = As_ + 2560;
#pragma unroll
        for (int ks = 0; ks < 2; ks++) {
            const int kw = ks * 8 + kp;
            uint32_t a[4][4], b[4][2];
#pragma unroll
            for (int i = 0; i < 4; i++) {
                int r0 = awbase + i * 16;
                a[i][0] = As_[r0 * 20 + kw];
                a[i][1] = As_[(r0 + 8) * 20 + kw];
                a[i][2] = As_[r0 * 20 + kw + 4];
                a[i][3] = As_[(r0 + 8) * 20 + kw + 4];
            }
#pragma unroll
            for (int j = 0; j < 4; j++) {
                int n0 = bwbase + j * 8;
                b[j][0] = Bs_[n0 * 20 + kw];
                b[j][1] = Bs_[n0 * 20 + kw + 4];
            }
#pragma unroll
            for (int i = 0; i < 4; i++)
#pragma unroll
                for (int j = 0; j < 4; j++)
                    mma_bf16(acc[i][j], a[i], b[j]);
        }

        if (c + 1 < GKC) {
            __syncthreads();
            G_STS((c + 1) & 1);
            __syncthreads();
        }
    }

    // Epilogue
#pragma unroll
    for (int i = 0; i < 4; i++) {
        int m0 = mbase + wm * 64 + i * 16 + (lane >> 2);
#pragma unroll
        for (int j = 0; j < 4; j++) {
            int n0 = nbase + wn * 32 + j * 8 + (lane & 3) * 2;
            if constexpr (MODE == 0) {
                *(float2*)(C + (size_t)m0 * Ncols + n0) =
                    make_float2(acc[i][j][0], acc[i][j][1]);
                *(float2*)(C + (size_t)(m0 + 8) * Ncols + n0) =
                    make_float2(acc[i][j][2], acc[i][j][3]);
            } else {
                int mp = n0 / 768;
                int rr = n0 - mp * 768;
                int which = rr >> 8;
                int ccc = rr & 255;
                int hh = mp * 2 + (ccc >> 7);
                int dd = ccc & 127;
                float* dst = (which == 0) ? g_q : ((which == 1) ? g_k : g_v);
                int bb = m0 >> 11, ss = m0 & 2047;
                size_t base = (((size_t)(bb * Hh + hh) * Ss + ss) << 7) + dd;
                *(float2*)(dst + base) = make_float2(acc[i][j][0], acc[i][j][1]);
                // m0+8 is same bb (tile rows stay within one 2048 block: m0%2048 <= 2040)
                *(float2*)(dst + base + ((size_t)8 << 7)) =
                    make_float2(acc[i][j][2], acc[i][j][3]);
            }
        }
    }
}

// ---------------------------------------------------------------------------
// RoPE on first 32 dims of q,k.
// ---------------------------------------------------------------------------
__global__ void rope_kernel()
{
    int idx = blockIdx.x * blockDim.x + threadIdx.x;
    int i = idx & 15;
    int s = (idx >> 4) & (Ss - 1);
    int bh = idx >> 15;
    float inv_freq = powf(10000.f, -(float)i / 16.f);
    float ang = (float)s * inv_freq;
    float sn, cs;
    sincosf(ang, &sn, &cs);
    size_t base = (((size_t)bh * Ss + s) << 7) + 2 * i;
    float x0 = g_q[base], x1 = g_q[base + 1];
    g_q[base]     = x0 * cs - x1 * sn;
    g_q[base + 1] = x1 * cs + x0 * sn;
    x0 = g_k[base]; x1 = g_k[base + 1];
    g_k[base]     = x0 * cs - x1 * sn;
    g_k[base + 1] = x1 * cs + x0 * sn;
}

// ---------------------------------------------------------------------------
// Flash attention (GEMM-structured, fp32, causal) — unchanged.
// ---------------------------------------------------------------------------
#define ATTN_SMEM_BYTES 119808

__global__ __launch_bounds__(256) void attn2(
    const float* __restrict__ q, const float* __restrict__ k,
    const float* __restrict__ v, float* __restrict__ o)
{
    extern __shared__ float smf[];
    float* Qs = smf;
    float* Ks = smf + 16896;
    float* Vs = Ks + 4608;
    float* Ps = Vs + 4224;

    const int qt = (int)gridDim.x - 1 - (int)blockIdx.x;
    const int h = blockIdx.y, b = blockIdx.z;
    const int tid = threadIdx.x;
    const int ty = tid >> 4, tx = tid & 15;
    const int qbase = qt * 128;
    const size_t hb = ((size_t)(b * Hh + h)) * Ss * Dh;
    const float scale = 0.08838834764831845f;

    {
        int r = tid >> 1;
        int d0 = (tid & 1) * 64;
        const float4* qg = (const float4*)(q + hb + ((size_t)(qbase + r) << 7) + d0);
#pragma unroll
        for (int t = 0; t < 16; t++) {
            float4 vv = qg[t];
            int d = d0 + t * 4;
            Qs[(d + 0) * 132 + r] = vv.x * scale;
            Qs[(d + 1) * 132 + r] = vv.y * scale;
            Qs[(d + 2) * 132 + r] = vv.z * scale;
            Qs[(d + 3) * 132 + r] = vv.w * scale;
        }
    }

    float acc[8][8];
#pragma unroll
    for (int i = 0; i < 8; i++)
#pragma unroll
        for (int j = 0; j < 8; j++) acc[i][j] = 0.f;
    float m[8], l[8];
#pragma unroll
    for (int i = 0; i < 8; i++) { m[i] = -1e30f; l[i] = 0.f; }

    const int ntiles = qt * 4 + 4;
    for (int t0 = 0; t0 < ntiles; t0++) {
        const int j0 = t0 * 32;
        __syncthreads();
        {
            int kv = tid & 31, c = tid >> 5;
            const float4* kg = (const float4*)(k + hb + ((size_t)(j0 + kv) << 7) + c * 16);
#pragma unroll
            for (int t = 0; t < 4; t++) {
                float4 vv = kg[t];
                int d = c * 16 + t * 4;
                Ks[(d + 0) * 36 + kv] = vv.x;
                Ks[(d + 1) * 36 + kv] = vv.y;
                Ks[(d + 2) * 36 + kv] = vv.z;
                Ks[(d + 3) * 36 + kv] = vv.w;
            }
        }
        {
            int kv = tid >> 3, d0 = (tid & 7) * 16;
            const float4* vg = (const float4*)(v + hb + ((size_t)(j0 + kv) << 7) + d0);
            float4* vs = (float4*)(Vs + kv * 132 + d0);
#pragma unroll
            for (int t = 0; t < 4; t++) vs[t] = vg[t];
        }
        __syncthreads();

        float s[8][2];
#pragma unroll
        for (int i = 0; i < 8; i++) { s[i][0] = 0.f; s[i][1] = 0.f; }
#pragma unroll 8
        for (int kk = 0; kk < 128; kk++) {
            float4 a0 = *(const float4*)&Qs[kk * 132 + ty * 8];
            float4 a1 = *(const float4*)&Qs[kk * 132 + ty * 8 + 4];
            float2 bb = *(const float2*)&Ks[kk * 36 + tx * 2];
            float av[8] = {a0.x, a0.y, a0.z, a0.w, a1.x, a1.y, a1.z, a1.w};
#pragma unroll
            for (int i = 0; i < 8; i++) {
                s[i][0] += av[i] * bb.x;
                s[i][1] += av[i] * bb.y;
            }
        }

        if (j0 + 31 > qbase) {
#pragma unroll
            for (int i = 0; i < 8; i++) {
                int row = qbase + ty * 8 + i;
                if (j0 + tx * 2 + 0 > row) s[i][0] = -1e9f;
                if (j0 + tx * 2 + 1 > row) s[i][1] = -1e9f;
            }
        }

#pragma unroll
        for (int i = 0; i < 8; i++) {
            float cm = fmaxf(s[i][0], s[i][1]);
            cm = fmaxf(cm, __shfl_xor_sync(0xffffffffu, cm, 1));
            cm = fmaxf(cm, __shfl_xor_sync(0xffffffffu, cm, 2));
            cm = fmaxf(cm, __shfl_xor_sync(0xffffffffu, cm, 4));
            cm = fmaxf(cm, __shfl_xor_sync(0xffffffffu, cm, 8));
            float mn = fmaxf(m[i], cm);
            float corr = __expf(m[i] - mn);
            m[i] = mn;
            float p0 = __expf(s[i][0] - mn);
            float p1 = __expf(s[i][1] - mn);
            float ps = p0 + p1;
            ps += __shfl_xor_sync(0xffffffffu, ps, 1);
            ps += __shfl_xor_sync(0xffffffffu, ps, 2);
            ps += __shfl_xor_sync(0xffffffffu, ps, 4);
            ps += __shfl_xor_sync(0xffffffffu, ps, 8);
            l[i] = l[i] * corr + ps;
            Ps[(tx * 2 + 0) * 132 + ty * 8 + i] = p0;
            Ps[(tx * 2 + 1) * 132 + ty * 8 + i] = p1;
#pragma unroll
            for (int j = 0; j < 8; j++) acc[i][j] *= corr;
        }
        __syncthreads();

#pragma unroll 4
        for (int p = 0; p < 32; p++) {
            float4 pa0 = *(const float4*)&Ps[p * 132 + ty * 8];
            float4 pa1 = *(const float4*)&Ps[p * 132 + ty * 8 + 4];
            float4 vb0 = *(const float4*)&Vs[p * 132 + tx * 8];
            float4 vb1 = *(const float4*)&Vs[p * 132 + tx * 8 + 4];
            float pa[8] = {pa0.x, pa0.y, pa0.z, pa0.w, pa1.x, pa1.y, pa1.z, pa1.w};
            float vb[8] = {vb0.x, vb0.y, vb0.z, vb0.w, vb1.x, vb1.y, vb1.z, vb1.w};
#pragma unroll
            for (int i = 0; i < 8; i++)
#pragma unroll
                for (int j = 0; j < 8; j++) acc[i][j] += pa[i] * vb[j];
        }
    }

#pragma unroll
    for (int i = 0; i < 8; i++) {
        float inv = 1.f / l[i];
        int r = qbase + ty * 8 + i;
        float4* op = (float4*)(o + (((size_t)(b * Ss + r)) << 11) + h * 128 + tx * 8);
        op[0] = make_float4(acc[i][0] * inv, acc[i][1] * inv, acc[i][2] * inv, acc[i][3] * inv);
        op[1] = make_float4(acc[i][4] * inv, acc[i][5] * inv, acc[i][6] * inv, acc[i][7] * inv);
    }
}

// ---------------------------------------------------------------------------
extern "C" void kernel_launch(void* const* d_in, const int* in_sizes, int n_in,
                              void* d_out, int out_size)
{
    const float* hidden = (const float*)d_in[0];
    const float* wqkv   = (const float*)d_in[1];
    const float* wout   = (const float*)d_in[2];
    float* out = (float*)d_out;

    float *pq, *pk, *pv, *pao;
    __nv_bfloat16 *pap, *pwqkv, *pwout;
    cudaGetSymbolAddress((void**)&pq,    g_q);
    cudaGetSymbolAddress((void**)&pk,    g_k);
    cudaGetSymbolAddress((void**)&pv,    g_v);
    cudaGetSymbolAddress((void**)&pao,   g_ao);
    cudaGetSymbolAddress((void**)&pap,   g_a_p);
    cudaGetSymbolAddress((void**)&pwqkv, g_wqkv_p);
    cudaGetSymbolAddress((void**)&pwout, g_wout_p);

    cudaFuncSetAttribute(attn2, cudaFuncAttributeMaxDynamicSharedMemorySize,
                         ATTN_SMEM_BYTES);

    // Pack weights + activations into 3-term bf16 split form
    {
        int t4 = (3 * Ee * Ee) / 4;
        pack_kernel<0><<<(t4 + 255) / 256, 256>>>(wqkv, pwqkv, t4);
        t4 = (Ee * Ee) / 4;
        pack_kernel<0><<<(t4 + 255) / 256, 256>>>(wout, pwout, t4);
        t4 = (Bb * Ss * Ee) / 4;
        pack_kernel<1><<<(t4 + 255) / 256, 256>>>(hidden, pap, t4);
    }
    // 1) QKV projection (HMMA) + scatter into [B,H,S,D]
    {
        dim3 grid(3 * Ee / 128, Bb * Ss / 128);  // (48, 32)
        gemm_mma<1><<<grid, 256>>>(pap, pwqkv, nullptr, 0);
    }
    // 2) RoPE
    rope_kernel<<<(Bb * Hh * Ss * 16) / 256, 256>>>();
    // 3) Attention -> g_ao [B,S,E]
    {
        dim3 grid(Ss / 128, Hh, Bb);
        attn2<<<grid, 256, ATTN_SMEM_BYTES>>>(pq, pk, pv, pao);
    }
    // 4) Pack attention output, out projection (HMMA)
    {
        int t4 = (Bb * Ss * Ee) / 4;
        pack_kernel<1><<<(t4 + 255) / 256, 256>>>(pao, pap, t4);
        dim3 grid(Ee / 128, Bb * Ss / 128);  // (16, 32)
        gemm_mma<0><<<grid, 256>>>(pap, pwout, out, Ee);
    }
}

// round 5
// speedup vs baseline: 4.5203x; 1.2080x over previous
#include <cuda_runtime.h>
#include <cuda_bf16.h>
#include <math.h>
#include <cstdint>

#define Bb 2
#define Ss 2048
#define Ee 2048
#define Hh 16
#define Dh 128
#define GK 6144          // packed K = 3 * 2048
#define GKC 192          // GK / 32 chunks

#define GSTAGES 4
#define STAGE_WORDS 5120                    // A 2560 + B 2560 words per stage
#define GEMM_SMEM_BYTES (GSTAGES * STAGE_WORDS * 4)   // 81920

// ---------------- scratch (__device__ globals; no allocation allowed) -------
__device__ float g_q[(size_t)Bb * Hh * Ss * Dh];
__device__ float g_k[(size_t)Bb * Hh * Ss * Dh];
__device__ float g_v[(size_t)Bb * Hh * Ss * Dh];
__device__ float g_ao[(size_t)Bb * Ss * Ee];
__device__ __nv_bfloat16 g_a_p[(size_t)Bb * Ss * GK];       // packed activations
__device__ __nv_bfloat16 g_wqkv_p[(size_t)3 * Ee * GK];     // packed Wqkv
__device__ __nv_bfloat16 g_wout_p[(size_t)Ee * GK];         // packed Wout

__device__ __forceinline__ uint32_t smem_u32(const void* p) {
    uint32_t a;
    asm("{ .reg .u64 t; cvta.to.shared.u64 t, %1; cvt.u32.u64 %0, t; }"
        : "=r"(a) : "l"(p));
    return a;
}

// ---------------------------------------------------------------------------
// Packing kernels: fp32 -> 3-term bf16 split along K.
// A-pack: [Ah | Ah | Al]   B-pack: [Bh | Bl | Bh]
// ---------------------------------------------------------------------------
__device__ __forceinline__ void split_bf16(float x, __nv_bfloat16& h, __nv_bfloat16& l) {
    h = __float2bfloat16(x);
    l = __float2bfloat16(x - __bfloat162float(h));
}

template <int ISA>
__global__ __launch_bounds__(256) void pack_kernel(
    const float* __restrict__ src, __nv_bfloat16* __restrict__ dst, int total4)
{
    int i = blockIdx.x * blockDim.x + threadIdx.x;
    if (i >= total4) return;
    int r = i >> 9;
    int k4 = (i & 511) * 4;
    float4 x = *(const float4*)(src + ((size_t)r << 11) + k4);
    __nv_bfloat16 h[4], l[4];
    split_bf16(x.x, h[0], l[0]); split_bf16(x.y, h[1], l[1]);
    split_bf16(x.z, h[2], l[2]); split_bf16(x.w, h[3], l[3]);
    size_t rb = (size_t)r * GK + k4;
    __nv_bfloat162 hp0 = {h[0], h[1]}, hp1 = {h[2], h[3]};
    __nv_bfloat162 lp0 = {l[0], l[1]}, lp1 = {l[2], l[3]};
    *(__nv_bfloat162*)(dst + rb + 0) = hp0; *(__nv_bfloat162*)(dst + rb + 2) = hp1;
    if (ISA) {
        *(__nv_bfloat162*)(dst + rb + 2048) = hp0; *(__nv_bfloat162*)(dst + rb + 2050) = hp1;
        *(__nv_bfloat162*)(dst + rb + 4096) = lp0; *(__nv_bfloat162*)(dst + rb + 4098) = lp1;
    } else {
        *(__nv_bfloat162*)(dst + rb + 2048) = lp0; *(__nv_bfloat162*)(dst + rb + 2050) = lp1;
        *(__nv_bfloat162*)(dst + rb + 4096) = hp0; *(__nv_bfloat162*)(dst + rb + 4098) = hp1;
    }
}

// ---------------------------------------------------------------------------
// mma.sync bf16 GEMM, cp.async 4-stage pipeline + ldmatrix fragments.
// CTA tile 128x128, 8 warps (2M x 4N), warp tile 64x32, K-chunk 32.
// Row pitch 20 words (80B): ldmatrix rows land on distinct 16B banks.
// ---------------------------------------------------------------------------
__device__ __forceinline__ void mma_bf16(float* c, const uint32_t* a, const uint32_t* b) {
    asm volatile(
        "mma.sync.aligned.m16n8k16.row.col.f32.bf16.bf16.f32 "
        "{%0,%1,%2,%3}, {%4,%5,%6,%7}, {%8,%9}, {%0,%1,%2,%3};"
        : "+f"(c[0]), "+f"(c[1]), "+f"(c[2]), "+f"(c[3])
        : "r"(a[0]), "r"(a[1]), "r"(a[2]), "r"(a[3]), "r"(b[0]), "r"(b[1]));
}

__device__ __forceinline__ void ldsm_x4(uint32_t* r, uint32_t addr) {
    asm volatile("ldmatrix.sync.aligned.m8n8.x4.shared.b16 {%0,%1,%2,%3}, [%4];"
        : "=r"(r[0]), "=r"(r[1]), "=r"(r[2]), "=r"(r[3]) : "r"(addr));
}

template <int MODE>
__global__ __launch_bounds__(256, 2) void gemm_mma(
    const __nv_bfloat16* __restrict__ A, const __nv_bfloat16* __restrict__ Bw,
    float* __restrict__ C, int Ncols)
{
    extern __shared__ __align__(16) uint32_t gsm[];
    const uint32_t sbase = smem_u32(gsm);

    const int tid = threadIdx.x;
    const int lane = tid & 31, w = tid >> 5;
    const int wm = w & 1, wn = w >> 1;
    const int mbase = blockIdx.y * 128, nbase = blockIdx.x * 128;

    float acc[4][4][4];
#pragma unroll
    for (int i = 0; i < 4; i++)
#pragma unroll
        for (int j = 0; j < 4; j++)
#pragma unroll
            for (int r = 0; r < 4; r++) acc[i][j][r] = 0.f;

    // cp.async producer pattern: thread -> (row = tid>>2, 16B seg = tid&3),
    // plus the same at row+64; for both A and B tiles.
    const int grow = tid >> 2, gseg = tid & 3;
    const __nv_bfloat16* Ag = A + (size_t)(mbase + grow) * GK + gseg * 8;
    const __nv_bfloat16* Bg = Bw + (size_t)(nbase + grow) * GK + gseg * 8;
    const size_t rstep = (size_t)64 * GK;
    const uint32_t dbase = (grow * 20 + gseg * 4) * 4;   // byte offset in stage

#define ISSUE(c) do {                                                          \
    uint32_t d0 = sbase + (((c) & 3) * STAGE_WORDS) * 4 + dbase;               \
    const __nv_bfloat16* sA = Ag + (size_t)(c) * 32;                           \
    const __nv_bfloat16* sB = Bg + (size_t)(c) * 32;                           \
    asm volatile("cp.async.cg.shared.global [%0], [%1], 16;" :: "r"(d0), "l"(sA)); \
    asm volatile("cp.async.cg.shared.global [%0], [%1], 16;" :: "r"(d0 + 5120), "l"(sA + rstep)); \
    asm volatile("cp.async.cg.shared.global [%0], [%1], 16;" :: "r"(d0 + 10240), "l"(sB)); \
    asm volatile("cp.async.cg.shared.global [%0], [%1], 16;" :: "r"(d0 + 15360), "l"(sB + rstep)); \
} while (0)
#define COMMIT() asm volatile("cp.async.commit_group;" ::: "memory")
#define WAITG2() asm volatile("cp.async.wait_group 2;" ::: "memory")

    ISSUE(0); COMMIT();
    ISSUE(1); COMMIT();
    ISSUE(2); COMMIT();

    // ldmatrix per-lane address components (byte offsets within a stage)
    const int lane8 = lane & 7;
    const uint32_t aAddr = (uint32_t)((wm * 64 + ((lane >> 3) & 1) * 8 + lane8) * 80
                                      + (lane >> 4) * 16);
    const uint32_t bAddr = (uint32_t)(10240 + (wn * 32 + (lane >> 4) * 8 + lane8) * 80
                                      + ((lane >> 3) & 1) * 16);

    for (int c = 0; c < GKC; c++) {
        WAITG2();
        __syncthreads();
        if (c + 3 < GKC) ISSUE(c + 3);
        COMMIT();

        const uint32_t st = sbase + ((c & 3) * STAGE_WORDS) * 4;
#pragma unroll
        for (int ks = 0; ks < 2; ks++) {
            uint32_t a[4][4], b[2][4];
#pragma unroll
            for (int i = 0; i < 4; i++)
                ldsm_x4(a[i], st + aAddr + i * 16 * 80 + ks * 32);
#pragma unroll
            for (int jp = 0; jp < 2; jp++)
                ldsm_x4(b[jp], st + bAddr + jp * 16 * 80 + ks * 32);
#pragma unroll
            for (int i = 0; i < 4; i++)
#pragma unroll
                for (int j = 0; j < 4; j++)
                    mma_bf16(acc[i][j], a[i], &b[j >> 1][(j & 1) * 2]);
        }
    }

    // Epilogue
#pragma unroll
    for (int i = 0; i < 4; i++) {
        int m0 = mbase + wm * 64 + i * 16 + (lane >> 2);
#pragma unroll
        for (int j = 0; j < 4; j++) {
            int n0 = nbase + wn * 32 + j * 8 + (lane & 3) * 2;
            if constexpr (MODE == 0) {
                *(float2*)(C + (size_t)m0 * Ncols + n0) =
                    make_float2(acc[i][j][0], acc[i][j][1]);
                *(float2*)(C + (size_t)(m0 + 8) * Ncols + n0) =
                    make_float2(acc[i][j][2], acc[i][j][3]);
            } else {
                int mp = n0 / 768;
                int rr = n0 - mp * 768;
                int which = rr >> 8;
                int ccc = rr & 255;
                int hh = mp * 2 + (ccc >> 7);
                int dd = ccc & 127;
                float* dst = (which == 0) ? g_q : ((which == 1) ? g_k : g_v);
                int bb = m0 >> 11, ss = m0 & 2047;
                size_t base = (((size_t)(bb * Hh + hh) * Ss + ss) << 7) + dd;
                *(float2*)(dst + base) = make_float2(acc[i][j][0], acc[i][j][1]);
                *(float2*)(dst + base + ((size_t)8 << 7)) =
                    make_float2(acc[i][j][2], acc[i][j][3]);
            }
        }
    }
}

// ---------------------------------------------------------------------------
// RoPE on first 32 dims of q,k.
// ---------------------------------------------------------------------------
__global__ void rope_kernel()
{
    int idx = blockIdx.x * blockDim.x + threadIdx.x;
    int i = idx & 15;
    int s = (idx >> 4) & (Ss - 1);
    int bh = idx >> 15;
    float inv_freq = powf(10000.f, -(float)i / 16.f);
    float ang = (float)s * inv_freq;
    float sn, cs;
    sincosf(ang, &sn, &cs);
    size_t base = (((size_t)bh * Ss + s) << 7) + 2 * i;
    float x0 = g_q[base], x1 = g_q[base + 1];
    g_q[base]     = x0 * cs - x1 * sn;
    g_q[base + 1] = x1 * cs + x0 * sn;
    x0 = g_k[base]; x1 = g_k[base + 1];
    g_k[base]     = x0 * cs - x1 * sn;
    g_k[base + 1] = x1 * cs + x0 * sn;
}

// ---------------------------------------------------------------------------
// Flash attention (GEMM-structured, fp32, causal) — unchanged.
// ---------------------------------------------------------------------------
#define ATTN_SMEM_BYTES 119808

__global__ __launch_bounds__(256) void attn2(
    const float* __restrict__ q, const float* __restrict__ k,
    const float* __restrict__ v, float* __restrict__ o)
{
    extern __shared__ float smf[];
    float* Qs = smf;
    float* Ks = smf + 16896;
    float* Vs = Ks + 4608;
    float* Ps = Vs + 4224;

    const int qt = (int)gridDim.x - 1 - (int)blockIdx.x;
    const int h = blockIdx.y, b = blockIdx.z;
    const int tid = threadIdx.x;
    const int ty = tid >> 4, tx = tid & 15;
    const int qbase = qt * 128;
    const size_t hb = ((size_t)(b * Hh + h)) * Ss * Dh;
    const float scale = 0.08838834764831845f;

    {
        int r = tid >> 1;
        int d0 = (tid & 1) * 64;
        const float4* qg = (const float4*)(q + hb + ((size_t)(qbase + r) << 7) + d0);
#pragma unroll
        for (int t = 0; t < 16; t++) {
            float4 vv = qg[t];
            int d = d0 + t * 4;
            Qs[(d + 0) * 132 + r] = vv.x * scale;
            Qs[(d + 1) * 132 + r] = vv.y * scale;
            Qs[(d + 2) * 132 + r] = vv.z * scale;
            Qs[(d + 3) * 132 + r] = vv.w * scale;
        }
    }

    float acc[8][8];
#pragma unroll
    for (int i = 0; i < 8; i++)
#pragma unroll
        for (int j = 0; j < 8; j++) acc[i][j] = 0.f;
    float m[8], l[8];
#pragma unroll
    for (int i = 0; i < 8; i++) { m[i] = -1e30f; l[i] = 0.f; }

    const int ntiles = qt * 4 + 4;
    for (int t0 = 0; t0 < ntiles; t0++) {
        const int j0 = t0 * 32;
        __syncthreads();
        {
            int kv = tid & 31, c = tid >> 5;
            const float4* kg = (const float4*)(k + hb + ((size_t)(j0 + kv) << 7) + c * 16);
#pragma unroll
            for (int t = 0; t < 4; t++) {
                float4 vv = kg[t];
                int d = c * 16 + t * 4;
                Ks[(d + 0) * 36 + kv] = vv.x;
                Ks[(d + 1) * 36 + kv] = vv.y;
                Ks[(d + 2) * 36 + kv] = vv.z;
                Ks[(d + 3) * 36 + kv] = vv.w;
            }
        }
        {
            int kv = tid >> 3, d0 = (tid & 7) * 16;
            const float4* vg = (const float4*)(v + hb + ((size_t)(j0 + kv) << 7) + d0);
            float4* vs = (float4*)(Vs + kv * 132 + d0);
#pragma unroll
            for (int t = 0; t < 4; t++) vs[t] = vg[t];
        }
        __syncthreads();

        float s[8][2];
#pragma unroll
        for (int i = 0; i < 8; i++) { s[i][0] = 0.f; s[i][1] = 0.f; }
#pragma unroll 8
        for (int kk = 0; kk < 128; kk++) {
            float4 a0 = *(const float4*)&Qs[kk * 132 + ty * 8];
            float4 a1 = *(const float4*)&Qs[kk * 132 + ty * 8 + 4];
            float2 bb = *(const float2*)&Ks[kk * 36 + tx * 2];
            float av[8] = {a0.x, a0.y, a0.z, a0.w, a1.x, a1.y, a1.z, a1.w};
#pragma unroll
            for (int i = 0; i < 8; i++) {
                s[i][0] += av[i] * bb.x;
                s[i][1] += av[i] * bb.y;
            }
        }

        if (j0 + 31 > qbase) {
#pragma unroll
            for (int i = 0; i < 8; i++) {
                int row = qbase + ty * 8 + i;
                if (j0 + tx * 2 + 0 > row) s[i][0] = -1e9f;
                if (j0 + tx * 2 + 1 > row) s[i][1] = -1e9f;
            }
        }

#pragma unroll
        for (int i = 0; i < 8; i++) {
            float cm = fmaxf(s[i][0], s[i][1]);
            cm = fmaxf(cm, __shfl_xor_sync(0xffffffffu, cm, 1));
            cm = fmaxf(cm, __shfl_xor_sync(0xffffffffu, cm, 2));
            cm = fmaxf(cm, __shfl_xor_sync(0xffffffffu, cm, 4));
            cm = fmaxf(cm, __shfl_xor_sync(0xffffffffu, cm, 8));
            float mn = fmaxf(m[i], cm);
            float corr = __expf(m[i] - mn);
            m[i] = mn;
            float p0 = __expf(s[i][0] - mn);
            float p1 = __expf(s[i][1] - mn);
            float ps = p0 + p1;
            ps += __shfl_xor_sync(0xffffffffu, ps, 1);
            ps += __shfl_xor_sync(0xffffffffu, ps, 2);
            ps += __shfl_xor_sync(0xffffffffu, ps, 4);
            ps += __shfl_xor_sync(0xffffffffu, ps, 8);
            l[i] = l[i] * corr + ps;
            Ps[(tx * 2 + 0) * 132 + ty * 8 + i] = p0;
            Ps[(tx * 2 + 1) * 132 + ty * 8 + i] = p1;
#pragma unroll
            for (int j = 0; j < 8; j++) acc[i][j] *= corr;
        }
        __syncthreads();

#pragma unroll 4
        for (int p = 0; p < 32; p++) {
            float4 pa0 = *(const float4*)&Ps[p * 132 + ty * 8];
            float4 pa1 = *(const float4*)&Ps[p * 132 + ty * 8 + 4];
            float4 vb0 = *(const float4*)&Vs[p * 132 + tx * 8];
            float4 vb1 = *(const float4*)&Vs[p * 132 + tx * 8 + 4];
            float pa[8] = {pa0.x, pa0.y, pa0.z, pa0.w, pa1.x, pa1.y, pa1.z, pa1.w};
            float vb[8] = {vb0.x, vb0.y, vb0.z, vb0.w, vb1.x, vb1.y, vb1.z, vb1.w};
#pragma unroll
            for (int i = 0; i < 8; i++)
#pragma unroll
                for (int j = 0; j < 8; j++) acc[i][j] += pa[i] * vb[j];
        }
    }

#pragma unroll
    for (int i = 0; i < 8; i++) {
        float inv = 1.f / l[i];
        int r = qbase + ty * 8 + i;
        float4* op = (float4*)(o + (((size_t)(b * Ss + r)) << 11) + h * 128 + tx * 8);
        op[0] = make_float4(acc[i][0] * inv, acc[i][1] * inv, acc[i][2] * inv, acc[i][3] * inv);
        op[1] = make_float4(acc[i][4] * inv, acc[i][5] * inv, acc[i][6] * inv, acc[i][7] * inv);
    }
}

// ---------------------------------------------------------------------------
extern "C" void kernel_launch(void* const* d_in, const int* in_sizes, int n_in,
                              void* d_out, int out_size)
{
    const float* hidden = (const float*)d_in[0];
    const float* wqkv   = (const float*)d_in[1];
    const float* wout   = (const float*)d_in[2];
    float* out = (float*)d_out;

    float *pq, *pk, *pv, *pao;
    __nv_bfloat16 *pap, *pwqkv, *pwout;
    cudaGetSymbolAddress((void**)&pq,    g_q);
    cudaGetSymbolAddress((void**)&pk,    g_k);
    cudaGetSymbolAddress((void**)&pv,    g_v);
    cudaGetSymbolAddress((void**)&pao,   g_ao);
    cudaGetSymbolAddress((void**)&pap,   g_a_p);
    cudaGetSymbolAddress((void**)&pwqkv, g_wqkv_p);
    cudaGetSymbolAddress((void**)&pwout, g_wout_p);

    cudaFuncSetAttribute(gemm_mma<0>, cudaFuncAttributeMaxDynamicSharedMemorySize,
                         GEMM_SMEM_BYTES);
    cudaFuncSetAttribute(gemm_mma<1>, cudaFuncAttributeMaxDynamicSharedMemorySize,
                         GEMM_SMEM_BYTES);
    cudaFuncSetAttribute(attn2, cudaFuncAttributeMaxDynamicSharedMemorySize,
                         ATTN_SMEM_BYTES);

    // Pack weights + activations into 3-term bf16 split form
    {
        int t4 = (3 * Ee * Ee) / 4;
        pack_kernel<0><<<(t4 + 255) / 256, 256>>>(wqkv, pwqkv, t4);
        t4 = (Ee * Ee) / 4;
        pack_kernel<0><<<(t4 + 255) / 256, 256>>>(wout, pwout, t4);
        t4 = (Bb * Ss * Ee) / 4;
        pack_kernel<1><<<(t4 + 255) / 256, 256>>>(hidden, pap, t4);
    }
    // 1) QKV projection (HMMA) + scatter into [B,H,S,D]
    {
        dim3 grid(3 * Ee / 128, Bb * Ss / 128);  // (48, 32)
        gemm_mma<1><<<grid, 256, GEMM_SMEM_BYTES>>>(pap, pwqkv, nullptr, 0);
    }
    // 2) RoPE
    rope_kernel<<<(Bb * Hh * Ss * 16) / 256, 256>>>();
    // 3) Attention -> g_ao [B,S,E]
    {
        dim3 grid(Ss / 128, Hh, Bb);
        attn2<<<grid, 256, ATTN_SMEM_BYTES>>>(pq, pk, pv, pao);
    }
    // 4) Pack attention output, out projection (HMMA)
    {
        int t4 = (Bb * Ss * Ee) / 4;
        pack_kernel<1><<<(t4 + 255) / 256, 256>>>(pao, pap, t4);
        dim3 grid(Ee / 128, Bb * Ss / 128);  // (16, 32)
        gemm_mma<0><<<grid, 256, GEMM_SMEM_BYTES>>>(pap, pwout, out, Ee);
    }
}

// round 6
// speedup vs baseline: 7.2300x; 1.5994x over previous
#include <cuda_runtime.h>
#include <cuda_bf16.h>
#include <cuda_fp16.h>
#include <math.h>
#include <cstdint>

#define Bb 2
#define Ss 2048
#define Ee 2048
#define Hh 16
#define Dh 128
#define GK 6144          // packed K = 3 * 2048
#define GKC 192          // GK / 32 chunks

#define GSTAGES 4
#define STAGE_WORDS 5120
#define GEMM_SMEM_BYTES (GSTAGES * STAGE_WORDS * 4)   // 81920

// ---------------- scratch (__device__ globals; no allocation allowed) -------
__device__ __nv_bfloat16 g_a_p[(size_t)Bb * Ss * GK];       // packed activations
__device__ __nv_bfloat16 g_wqkv_p[(size_t)3 * Ee * GK];     // packed Wqkv
__device__ __nv_bfloat16 g_wout_p[(size_t)Ee * GK];         // packed Wout
__device__ __half g_qp[(size_t)Bb * Hh * Ss * 256];         // q fp16 [qh|ql], roped+scaled
__device__ __half g_kp[(size_t)Bb * Hh * Ss * 256];         // k fp16 [kh|kl], roped
__device__ __half g_vt[(size_t)Bb * Hh * 2 * Dh * Ss];      // V^T fp16 planes [vh][vl]

__device__ __forceinline__ uint32_t smem_u32(const void* p) {
    uint32_t a;
    asm("{ .reg .u64 t; cvta.to.shared.u64 t, %1; cvt.u32.u64 %0, t; }"
        : "=r"(a) : "l"(p));
    return a;
}

// ---------------------------------------------------------------------------
// Packing: fp32 -> 3-term bf16 split along K.  A:[h|h|l]  B:[h|l|h]
// ---------------------------------------------------------------------------
__device__ __forceinline__ void split_bf16(float x, __nv_bfloat16& h, __nv_bfloat16& l) {
    h = __float2bfloat16(x);
    l = __float2bfloat16(x - __bfloat162float(h));
}

template <int ISA>
__global__ __launch_bounds__(256) void pack_kernel(
    const float* __restrict__ src, __nv_bfloat16* __restrict__ dst, int total4)
{
    int i = blockIdx.x * blockDim.x + threadIdx.x;
    if (i >= total4) return;
    int r = i >> 9;
    int k4 = (i & 511) * 4;
    float4 x = *(const float4*)(src + ((size_t)r << 11) + k4);
    __nv_bfloat16 h[4], l[4];
    split_bf16(x.x, h[0], l[0]); split_bf16(x.y, h[1], l[1]);
    split_bf16(x.z, h[2], l[2]); split_bf16(x.w, h[3], l[3]);
    size_t rb = (size_t)r * GK + k4;
    __nv_bfloat162 hp0 = {h[0], h[1]}, hp1 = {h[2], h[3]};
    __nv_bfloat162 lp0 = {l[0], l[1]}, lp1 = {l[2], l[3]};
    *(__nv_bfloat162*)(dst + rb + 0) = hp0; *(__nv_bfloat162*)(dst + rb + 2) = hp1;
    if (ISA) {
        *(__nv_bfloat162*)(dst + rb + 2048) = hp0; *(__nv_bfloat162*)(dst + rb + 2050) = hp1;
        *(__nv_bfloat162*)(dst + rb + 4096) = lp0; *(__nv_bfloat162*)(dst + rb + 4098) = lp1;
    } else {
        *(__nv_bfloat162*)(dst + rb + 2048) = lp0; *(__nv_bfloat162*)(dst + rb + 2050) = lp1;
        *(__nv_bfloat162*)(dst + rb + 4096) = hp0; *(__nv_bfloat162*)(dst + rb + 4098) = hp1;
    }
}

// ---------------------------------------------------------------------------
// mma helpers
// ---------------------------------------------------------------------------
__device__ __forceinline__ void mma_bf16(float* c, const uint32_t* a, const uint32_t* b) {
    asm volatile(
        "mma.sync.aligned.m16n8k16.row.col.f32.bf16.bf16.f32 "
        "{%0,%1,%2,%3}, {%4,%5,%6,%7}, {%8,%9}, {%0,%1,%2,%3};"
        : "+f"(c[0]), "+f"(c[1]), "+f"(c[2]), "+f"(c[3])
        : "r"(a[0]), "r"(a[1]), "r"(a[2]), "r"(a[3]), "r"(b[0]), "r"(b[1]));
}
__device__ __forceinline__ void mma_fp16(float* c, const uint32_t* a, const uint32_t* b) {
    asm volatile(
        "mma.sync.aligned.m16n8k16.row.col.f32.f16.f16.f32 "
        "{%0,%1,%2,%3}, {%4,%5,%6,%7}, {%8,%9}, {%0,%1,%2,%3};"
        : "+f"(c[0]), "+f"(c[1]), "+f"(c[2]), "+f"(c[3])
        : "r"(a[0]), "r"(a[1]), "r"(a[2]), "r"(a[3]), "r"(b[0]), "r"(b[1]));
}
__device__ __forceinline__ void ldsm_x4(uint32_t* r, uint32_t addr) {
    asm volatile("ldmatrix.sync.aligned.m8n8.x4.shared.b16 {%0,%1,%2,%3}, [%4];"
        : "=r"(r[0]), "=r"(r[1]), "=r"(r[2]), "=r"(r[3]) : "r"(addr));
}

// ---------------------------------------------------------------------------
// Projection GEMM (bf16 3-term split, cp.async + ldmatrix), as in R5.
// MODE 0: fp32 store to C.  MODE 1: QKV epilogue with fused rope + fp16
// split-pack of q,k and split-transpose of v.
// ---------------------------------------------------------------------------
template <int MODE>
__global__ __launch_bounds__(256, 2) void gemm_mma(
    const __nv_bfloat16* __restrict__ A, const __nv_bfloat16* __restrict__ Bw,
    float* __restrict__ C, int Ncols)
{
    extern __shared__ __align__(16) uint32_t gsm[];
    const uint32_t sbase = smem_u32(gsm);

    const int tid = threadIdx.x;
    const int lane = tid & 31, w = tid >> 5;
    const int wm = w & 1, wn = w >> 1;
    const int mbase = blockIdx.y * 128, nbase = blockIdx.x * 128;

    float acc[4][4][4];
#pragma unroll
    for (int i = 0; i < 4; i++)
#pragma unroll
        for (int j = 0; j < 4; j++)
#pragma unroll
            for (int r = 0; r < 4; r++) acc[i][j][r] = 0.f;

    const int grow = tid >> 2, gseg = tid & 3;
    const __nv_bfloat16* Ag = A + (size_t)(mbase + grow) * GK + gseg * 8;
    const __nv_bfloat16* Bg = Bw + (size_t)(nbase + grow) * GK + gseg * 8;
    const size_t rstep = (size_t)64 * GK;
    const uint32_t dbase = (grow * 20 + gseg * 4) * 4;

#define ISSUE(c) do {                                                          \
    uint32_t d0 = sbase + (((c) & 3) * STAGE_WORDS) * 4 + dbase;               \
    const __nv_bfloat16* sA = Ag + (size_t)(c) * 32;                           \
    const __nv_bfloat16* sB = Bg + (size_t)(c) * 32;                           \
    asm volatile("cp.async.cg.shared.global [%0], [%1], 16;" :: "r"(d0), "l"(sA)); \
    asm volatile("cp.async.cg.shared.global [%0], [%1], 16;" :: "r"(d0 + 5120), "l"(sA + rstep)); \
    asm volatile("cp.async.cg.shared.global [%0], [%1], 16;" :: "r"(d0 + 10240), "l"(sB)); \
    asm volatile("cp.async.cg.shared.global [%0], [%1], 16;" :: "r"(d0 + 15360), "l"(sB + rstep)); \
} while (0)
#define COMMIT() asm volatile("cp.async.commit_group;" ::: "memory")
#define WAITG2() asm volatile("cp.async.wait_group 2;" ::: "memory")

    ISSUE(0); COMMIT();
    ISSUE(1); COMMIT();
    ISSUE(2); COMMIT();

    const int lane8 = lane & 7;
    const uint32_t aAddr = (uint32_t)((wm * 64 + ((lane >> 3) & 1) * 8 + lane8) * 80
                                      + (lane >> 4) * 16);
    const uint32_t bAddr = (uint32_t)(10240 + (wn * 32 + (lane >> 4) * 8 + lane8) * 80
                                      + ((lane >> 3) & 1) * 16);

    for (int c = 0; c < GKC; c++) {
        WAITG2();
        __syncthreads();
        if (c + 3 < GKC) ISSUE(c + 3);
        COMMIT();

        const uint32_t st = sbase + ((c & 3) * STAGE_WORDS) * 4;
#pragma unroll
        for (int ks = 0; ks < 2; ks++) {
            uint32_t a[4][4], b[2][4];
#pragma unroll
            for (int i = 0; i < 4; i++)
                ldsm_x4(a[i], st + aAddr + i * 16 * 80 + ks * 32);
#pragma unroll
            for (int jp = 0; jp < 2; jp++)
                ldsm_x4(b[jp], st + bAddr + jp * 16 * 80 + ks * 32);
#pragma unroll
            for (int i = 0; i < 4; i++)
#pragma unroll
                for (int j = 0; j < 4; j++)
                    mma_bf16(acc[i][j], a[i], &b[j >> 1][(j & 1) * 2]);
        }
    }

#pragma unroll
    for (int i = 0; i < 4; i++) {
        int m0 = mbase + wm * 64 + i * 16 + (lane >> 2);
#pragma unroll
        for (int j = 0; j < 4; j++) {
            int n0 = nbase + wn * 32 + j * 8 + (lane & 3) * 2;
            if constexpr (MODE == 0) {
                *(float2*)(C + (size_t)m0 * Ncols + n0) =
                    make_float2(acc[i][j][0], acc[i][j][1]);
                *(float2*)(C + (size_t)(m0 + 8) * Ncols + n0) =
                    make_float2(acc[i][j][2], acc[i][j][3]);
            } else {
                int mp = n0 / 768;
                int rr = n0 - mp * 768;
                int which = rr >> 8;
                int ccc = rr & 255;
                int hh = mp * 2 + (ccc >> 7);
                int dd = ccc & 127;
                int bb = m0 >> 11, ss = m0 & 2047;
                int bh2 = bb * Hh + hh;
                float v0 = acc[i][j][0], v1 = acc[i][j][1];
                float v2 = acc[i][j][2], v3 = acc[i][j][3];
                if (which == 2) {
                    // V: split-transpose into g_vt planes [vh|vl], [d][s]
                    size_t vb = ((size_t)bh2 * 2 * Dh + dd) * (size_t)Ss + ss;
                    const size_t PL = (size_t)Dh * Ss;   // 262144
                    __half a0 = __float2half(v0);
                    g_vt[vb] = a0;
                    g_vt[vb + PL] = __float2half(v0 - __half2float(a0));
                    __half a1 = __float2half(v1);
                    g_vt[vb + Ss] = a1;
                    g_vt[vb + Ss + PL] = __float2half(v1 - __half2float(a1));
                    __half a2 = __float2half(v2);
                    g_vt[vb + 8] = a2;
                    g_vt[vb + 8 + PL] = __float2half(v2 - __half2float(a2));
                    __half a3 = __float2half(v3);
                    g_vt[vb + Ss + 8] = a3;
                    g_vt[vb + Ss + 8 + PL] = __float2half(v3 - __half2float(a3));
                } else {
                    // q/k: rope on dims < 32 (thread holds the full pair), then
                    // fp16 hi/lo split; q additionally scaled by 1/sqrt(Dh).
                    if (dd < 32) {
                        int ir = dd >> 1;
                        float f = powf(10000.f, -(float)ir * 0.0625f);
                        float s1, c1, s2, c2;
                        sincosf((float)ss * f, &s1, &c1);
                        sincosf((float)(ss + 8) * f, &s2, &c2);
                        float t0 = v0 * c1 - v1 * s1; v1 = v1 * c1 + v0 * s1; v0 = t0;
                        t0 = v2 * c2 - v3 * s2; v3 = v3 * c2 + v2 * s2; v2 = t0;
                    }
                    if (which == 0) {
                        const float sc = 0.08838834764831845f;
                        v0 *= sc; v1 *= sc; v2 *= sc; v3 *= sc;
                    }
                    __half* P = (which == 0) ? g_qp : g_kp;
                    size_t rb = ((size_t)bh2 * Ss + ss) * 256 + dd;
                    __half h0 = __float2half(v0), h1 = __float2half(v1);
                    __half h2 = __float2half(v2), h3 = __float2half(v3);
                    __half l0 = __float2half(v0 - __half2float(h0));
                    __half l1 = __float2half(v1 - __half2float(h1));
                    __half l2 = __float2half(v2 - __half2float(h2));
                    __half l3 = __float2half(v3 - __half2float(h3));
                    *(__half2*)(P + rb) = __halves2half2(h0, h1);
                    *(__half2*)(P + rb + 128) = __halves2half2(l0, l1);
                    *(__half2*)(P + rb + 8 * 256) = __halves2half2(h2, h3);
                    *(__half2*)(P + rb + 8 * 256 + 128) = __halves2half2(l2, l3);
                }
            }
        }
    }
}

// ---------------------------------------------------------------------------
// Tensor-core flash attention.  CTA = 128 q rows, 8 warps (16 q rows each).
// QK: 3 fp16 passes (qh*kh + qh*kl + ql*kh), K'=384.  PV: 2 passes (p*vh +
// p*vl).  Softmax fp32 in fragments, row reductions intra-warp (shfl 1,2).
// Epilogue writes bf16 3-term A-pack directly into g_a_p.
// smem: Qs 128x264h + Ks 64x264h + Vs 128x136h + Ps 128x72h = 154624 B.
// ---------------------------------------------------------------------------
#define ATTN3_SMEM 154624

__global__ __launch_bounds__(256, 1) void attn3(
    const __half* __restrict__ qp, const __half* __restrict__ kp,
    const __half* __restrict__ vt)
{
    extern __shared__ char sm3[];
    const uint32_t sb = smem_u32(sm3);
    const uint32_t Qs = sb;
    const uint32_t Ks = sb + 67584;
    const uint32_t Vs = sb + 101376;
    const uint32_t Ps = sb + 136192;
    char* PsC = sm3 + 136192;

    const int qb = (int)gridDim.x - 1 - (int)blockIdx.x;   // long blocks first
    const int h = blockIdx.y, b = blockIdx.z;
    const int bh = b * Hh + h;
    const int tid = threadIdx.x, lane = tid & 31, w = tid >> 5;
    const int qbase = qb * 128;

    // Q tile 128 x 256 halves -> Qs (pitch 528 B)
    {
        const __half* qg = qp + ((size_t)bh * Ss + qbase) * 256;
#pragma unroll
        for (int t = 0; t < 16; t++) {
            int u = tid + t * 256;
            int r = u >> 5, sg = u & 31;
            uint32_t dst = Qs + r * 528 + sg * 16;
            asm volatile("cp.async.cg.shared.global [%0], [%1], 16;"
                         :: "r"(dst), "l"(qg + r * 256 + sg * 8));
        }
        asm volatile("cp.async.commit_group;" ::: "memory");
    }

    float O[16][4];
#pragma unroll
    for (int i = 0; i < 16; i++)
#pragma unroll
        for (int r = 0; r < 4; r++) O[i][r] = 0.f;
    float m[2] = {-1e30f, -1e30f}, l[2] = {0.f, 0.f};

    const uint32_t aQ = Qs + (w * 16 + (lane & 15)) * 528 + (lane >> 4) * 16;
    const uint32_t bK = Ks + ((lane >> 4) * 8 + (lane & 7)) * 528 + ((lane >> 3) & 1) * 16;
    const uint32_t aP = Ps + (w * 16 + (lane & 15)) * 144 + (lane >> 4) * 16;
    const uint32_t bV = Vs + ((lane >> 4) * 8 + (lane & 7)) * 272 + ((lane >> 3) & 1) * 16;

    const int ntiles = 2 * qb + 2;
    for (int t = 0; t < ntiles; t++) {
        const int j0 = t * 64;
        __syncthreads();   // prior tile's smem reads complete
        {
            const __half* kg = kp + ((size_t)bh * Ss + j0) * 256;
#pragma unroll
            for (int tt = 0; tt < 8; tt++) {
                int u = tid + tt * 256;
                int r = u >> 5, sg = u & 31;
                uint32_t dst = Ks + r * 528 + sg * 16;
                asm volatile("cp.async.cg.shared.global [%0], [%1], 16;"
                             :: "r"(dst), "l"(kg + r * 256 + sg * 8));
            }
        }
        {
            const __half* vg = vt + (size_t)bh * 2 * Dh * Ss + j0;
#pragma unroll
            for (int tt = 0; tt < 8; tt++) {
                int u = tid + tt * 256;
                int pd = u >> 3, sg = u & 7;
                int pl = pd >> 7, d = pd & 127;
                uint32_t dst = Vs + d * 272 + pl * 128 + sg * 16;
                asm volatile("cp.async.cg.shared.global [%0], [%1], 16;"
                             :: "r"(dst), "l"(vg + (size_t)pd * Ss + sg * 8));
            }
        }
        asm volatile("cp.async.commit_group;" ::: "memory");
        asm volatile("cp.async.wait_group 0;" ::: "memory");
        __syncthreads();

        // ---- QK: scores s[8 ntiles][4] for warp rows w*16..w*16+15
        float s[8][4];
#pragma unroll
        for (int nt = 0; nt < 8; nt++)
#pragma unroll
            for (int r = 0; r < 4; r++) s[nt][r] = 0.f;
#pragma unroll
        for (int pass = 0; pass < 3; pass++) {
            const uint32_t ao = (pass == 2) ? 256u : 0u;   // ql segment
            const uint32_t bo = (pass == 1) ? 256u : 0u;   // kl segment
#pragma unroll
            for (int c = 0; c < 8; c++) {
                uint32_t a[4];
                ldsm_x4(a, aQ + ao + c * 32);
#pragma unroll
                for (int np = 0; np < 4; np++) {
                    uint32_t bf[4];
                    ldsm_x4(bf, bK + bo + c * 32 + np * (16 * 528));
                    mma_fp16(s[np * 2 + 0], a, &bf[0]);
                    mma_fp16(s[np * 2 + 1], a, &bf[2]);
                }
            }
        }

        // ---- causal mask (last two tiles only)
        if (t >= ntiles - 2) {
#pragma unroll
            for (int nt = 0; nt < 8; nt++)
#pragma unroll
                for (int r = 0; r < 4; r++) {
                    int grow = qbase + w * 16 + (lane >> 2) + (r >> 1) * 8;
                    int gcol = j0 + nt * 8 + (lane & 3) * 2 + (r & 1);
                    if (gcol > grow) s[nt][r] = -1e9f;
                }
        }

        // ---- online softmax
        float corr[2];
#pragma unroll
        for (int hh = 0; hh < 2; hh++) {
            float cm = -1e30f;
#pragma unroll
            for (int nt = 0; nt < 8; nt++)
                cm = fmaxf(cm, fmaxf(s[nt][hh * 2], s[nt][hh * 2 + 1]));
            cm = fmaxf(cm, __shfl_xor_sync(0xffffffffu, cm, 1));
            cm = fmaxf(cm, __shfl_xor_sync(0xffffffffu, cm, 2));
            float mn = fmaxf(m[hh], cm);
            corr[hh] = __expf(m[hh] - mn);
            m[hh] = mn;
            float ps = 0.f;
            int prow = w * 16 + (lane >> 2) + hh * 8;
#pragma unroll
            for (int nt = 0; nt < 8; nt++) {
                float p0 = __expf(s[nt][hh * 2] - mn);
                float p1 = __expf(s[nt][hh * 2 + 1] - mn);
                ps += p0 + p1;
                *(__half2*)(PsC + prow * 144 + (nt * 8 + (lane & 3) * 2) * 2) =
                    __floats2half2_rn(p0, p1);
            }
            ps += __shfl_xor_sync(0xffffffffu, ps, 1);
            ps += __shfl_xor_sync(0xffffffffu, ps, 2);
            l[hh] = l[hh] * corr[hh] + ps;
        }
#pragma unroll
        for (int i = 0; i < 16; i++) {
            O[i][0] *= corr[0]; O[i][1] *= corr[0];
            O[i][2] *= corr[1]; O[i][3] *= corr[1];
        }
        __syncthreads();   // Ps visible

        // ---- PV: O += P * (Vh ; Vl)
#pragma unroll
        for (int c = 0; c < 4; c++) {
            uint32_t a[4];
            ldsm_x4(a, aP + c * 32);
#pragma unroll
            for (int pass = 0; pass < 2; pass++) {
                const uint32_t bo = pass * 128u;
#pragma unroll
                for (int np = 0; np < 8; np++) {
                    uint32_t bf[4];
                    ldsm_x4(bf, bV + bo + c * 32 + np * (16 * 272));
                    mma_fp16(O[np * 2 + 0], a, &bf[0]);
                    mma_fp16(O[np * 2 + 1], a, &bf[2]);
                }
            }
        }
    }

    // ---- epilogue: normalize and write bf16 3-term A-pack into g_a_p
    float inv0 = 1.f / l[0], inv1 = 1.f / l[1];
#pragma unroll
    for (int nt = 0; nt < 16; nt++) {
        int col = h * 128 + nt * 8 + (lane & 3) * 2;
#pragma unroll
        for (int hh = 0; hh < 2; hh++) {
            float inv = hh ? inv1 : inv0;
            float o0 = O[nt][hh * 2] * inv;
            float o1 = O[nt][hh * 2 + 1] * inv;
            int srow = qbase + w * 16 + (lane >> 2) + hh * 8;
            size_t rb = ((size_t)(b * Ss + srow)) * GK + col;
            __nv_bfloat16 h0, l0b, h1, l1b;
            split_bf16(o0, h0, l0b);
            split_bf16(o1, h1, l1b);
            __nv_bfloat162 hp = {h0, h1}, lp = {l0b, l1b};
            *(__nv_bfloat162*)(g_a_p + rb) = hp;
            *(__nv_bfloat162*)(g_a_p + rb + 2048) = hp;
            *(__nv_bfloat162*)(g_a_p + rb + 4096) = lp;
        }
    }
}

// ---------------------------------------------------------------------------
extern "C" void kernel_launch(void* const* d_in, const int* in_sizes, int n_in,
                              void* d_out, int out_size)
{
    const float* hidden = (const float*)d_in[0];
    const float* wqkv   = (const float*)d_in[1];
    const float* wout   = (const float*)d_in[2];
    float* out = (float*)d_out;

    __nv_bfloat16 *pap, *pwqkv, *pwout;
    __half *pqp, *pkp, *pvt;
    cudaGetSymbolAddress((void**)&pap,   g_a_p);
    cudaGetSymbolAddress((void**)&pwqkv, g_wqkv_p);
    cudaGetSymbolAddress((void**)&pwout, g_wout_p);
    cudaGetSymbolAddress((void**)&pqp,   g_qp);
    cudaGetSymbolAddress((void**)&pkp,   g_kp);
    cudaGetSymbolAddress((void**)&pvt,   g_vt);

    cudaFuncSetAttribute(gemm_mma<0>, cudaFuncAttributeMaxDynamicSharedMemorySize,
                         GEMM_SMEM_BYTES);
    cudaFuncSetAttribute(gemm_mma<1>, cudaFuncAttributeMaxDynamicSharedMemorySize,
                         GEMM_SMEM_BYTES);
    cudaFuncSetAttribute(attn3, cudaFuncAttributeMaxDynamicSharedMemorySize,
                         ATTN3_SMEM);

    // Pack weights + activations (bf16 3-term split)
    {
        int t4 = (3 * Ee * Ee) / 4;
        pack_kernel<0><<<(t4 + 255) / 256, 256>>>(wqkv, pwqkv, t4);
        t4 = (Ee * Ee) / 4;
        pack_kernel<0><<<(t4 + 255) / 256, 256>>>(wout, pwout, t4);
        t4 = (Bb * Ss * Ee) / 4;
        pack_kernel<1><<<(t4 + 255) / 256, 256>>>(hidden, pap, t4);
    }
    // 1) QKV projection + fused rope/scale/fp16-pack epilogue
    {
        dim3 grid(3 * Ee / 128, Bb * Ss / 128);  // (48, 32)
        gemm_mma<1><<<grid, 256, GEMM_SMEM_BYTES>>>(pap, pwqkv, nullptr, 0);
    }
    // 2) Tensor-core flash attention -> bf16 A-pack in g_a_p
    {
        dim3 grid(Ss / 128, Hh, Bb);  // (16,16,2)
        attn3<<<grid, 256, ATTN3_SMEM>>>(pqp, pkp, pvt);
    }
    // 3) Output projection
    {
        dim3 grid(Ee / 128, Bb * Ss / 128);  // (16, 32)
        gemm_mma<0><<<grid, 256, GEMM_SMEM_BYTES>>>(pap, pwout, out, Ee);
    }
}